// round 8
// baseline (speedup 1.0000x reference)
#include <cuda_runtime.h>
#include <cuda_fp16.h>

#define BSZ 32
#define TT 512
#define DD 128
#define MM 50
#define NUMC 4096
#define AWC (NUMC + DD)
#define G4 512
#define RR (BSZ * TT)
#define WST 52

// ---------------- scratch (static device arrays; no allocation) ----------------
__device__ float g_w[RR * WST];
__device__ unsigned long long g_pack[RR * 2];
__device__ int g_prev[RR];
__device__ int g_match[RR];
__device__ float g_f[RR * DD];
__device__ float g_gi[RR * G4];
__device__ float g_H[RR * DD];
__device__ float g_C[RR * DD];
// precomputed fusion matrices
__device__ float g_We[DD * DD];
__device__ float g_Wa[DD * DD];
__device__ float g_ce[DD];
__device__ float g_ca[DD];
__device__ float g_Ae[NUMC * DD];
__device__ float g_Aa[NUMC * DD];
__device__ float g_KF[NUMC * DD];

__device__ __forceinline__ float warp_sum(float v) {
#pragma unroll
    for (int o = 16; o; o >>= 1) v += __shfl_xor_sync(0xffffffffu, v, o);
    return v;
}
__device__ __forceinline__ half2 as_h2(unsigned u) { return *reinterpret_cast<half2*>(&u); }
__device__ __forceinline__ float sigf(float x) { return 1.f / (1.f + __expf(-x)); }
__device__ __forceinline__ float h2sumf(half2 v) {
    const float2 e = __half22float2(v);
    return e.x + e.y;
}
__device__ __forceinline__ float ftanh(float x) {
    float y;
    asm("tanh.approx.f32 %0, %1;" : "=f"(y) : "f"(x));
    return y;
}

// ---------------- kP0: We/Wa (128x128) + ce/ca ---------------------------------
__global__ __launch_bounds__(128) void kP0(const float* __restrict__ aW,
                                           const float* __restrict__ eW,
                                           const float* __restrict__ addW,
                                           const float* __restrict__ ab,
                                           const float* __restrict__ eb,
                                           const float* __restrict__ addb) {
    const int o = blockIdx.x, j = threadIdx.x;
    float se = 0.f, sa = 0.f;
#pragma unroll 4
    for (int d = 0; d < DD; d++) {
        const float av = aW[d * AWC + NUMC + j];
        se = fmaf(av, eW[o * DD + d], se);
        sa = fmaf(av, addW[o * DD + d], sa);
    }
    g_We[o * DD + j] = se;
    g_Wa[o * DD + j] = sa;
    if (j == 0) {
        float ce = eb[o], ca = addb[o];
        for (int d = 0; d < DD; d++) {
            ce = fmaf(ab[d], eW[o * DD + d], ce);
            ca = fmaf(ab[d], addW[o * DD + d], ca);
        }
        g_ce[o] = ce;
        g_ca[o] = ca;
    }
}

// ---------------- kP1: A_e / A_a / KF (4096x128 each) --------------------------
__global__ __launch_bounds__(128) void kP1(const float* __restrict__ aW,
                                           const float* __restrict__ eW,
                                           const float* __restrict__ addW,
                                           const float* __restrict__ k_emb,
                                           const float* __restrict__ fW,
                                           const float* __restrict__ fb) {
    __shared__ float sA[DD][33];
    const int v = blockIdx.y;
    const int qv0 = blockIdx.x * 32;
    const int tid = threadIdx.x;
    if (v < 2) {
        const float4* s4 = (const float4*)(aW + (size_t)tid * AWC + qv0);
#pragma unroll
        for (int i = 0; i < 8; i++) {
            const float4 x = s4[i];
            sA[tid][4 * i] = x.x; sA[tid][4 * i + 1] = x.y;
            sA[tid][4 * i + 2] = x.z; sA[tid][4 * i + 3] = x.w;
        }
    } else {
#pragma unroll 4
        for (int i = 0; i < 32; i++) sA[tid][i] = k_emb[(size_t)(qv0 + i) * DD + tid];
    }
    __syncthreads();
    const int o = tid;
    const float* Brow = (v == 0) ? (eW + o * DD) : (v == 1) ? (addW + o * DD) : (fW + o * 256 + 128);
    const float bias = (v == 2) ? fb[o] : 0.f;
    float* dst = (v == 0) ? g_Ae : (v == 1) ? g_Aa : g_KF;
    for (int qv = 0; qv < 32; qv++) {
        float s0 = bias, s1 = 0.f;
#pragma unroll 8
        for (int d = 0; d < DD; d += 2) {
            s0 = fmaf(sA[d][qv], __ldg(&Brow[d]), s0);
            s1 = fmaf(sA[d + 1][qv], __ldg(&Brow[d + 1]), s1);
        }
        dst[(size_t)(qv0 + qv) * DD + o] = s0 + s1;
    }
}

// ---------------- Kernel A: gather + logits + softmax + quantize/pack ----------
__global__ __launch_bounds__(256) void kA(const int* __restrict__ q,
                                          const int* __restrict__ r,
                                          const float* __restrict__ k_emb,
                                          const float* __restrict__ Mk) {
    __shared__ float sMk[MM * DD];
    __shared__ float sk[DD];
    __shared__ float slog[MM];
    const int tid = threadIdx.x;
    for (int i = tid; i < MM * DD; i += 256) sMk[i] = Mk[i];
    const int base = blockIdx.x * 64;
    const int warp = tid >> 5, lane = tid & 31;

    for (int p = 0; p < 64; p++) {
        const int idx = base + p;
        __syncthreads();
        if (tid < DD) {
            const int qv = q[idx];
            sk[tid] = k_emb[qv * DD + tid];
        }
        __syncthreads();
        for (int m = warp; m < MM; m += 8) {
            float s = 0.f;
#pragma unroll
            for (int c = 0; c < 4; c++) s = fmaf(sk[c * 32 + lane], sMk[m * DD + c * 32 + lane], s);
            s = warp_sum(s);
            if (lane == 0) slog[m] = s;
        }
        __syncthreads();
        if (warp == 0) {
            float l0 = (lane < MM) ? slog[lane] : -1e30f;
            float l1 = (lane + 32 < MM) ? slog[lane + 32] : -1e30f;
            float mx = fmaxf(l0, l1);
#pragma unroll
            for (int o = 16; o; o >>= 1) mx = fmaxf(mx, __shfl_xor_sync(0xffffffffu, mx, o));
            float e0 = (lane < MM) ? expf(l0 - mx) : 0.f;
            float e1 = (lane + 32 < MM) ? expf(l1 - mx) : 0.f;
            float ssum = warp_sum(e0 + e1);
            float w0 = e0 / ssum, w1 = e1 / ssum;
            if (lane < MM) g_w[idx * WST + lane] = w0;
            if (lane + 32 < MM) g_w[idx * WST + lane + 32] = w1;
            if (lane == 0) { g_w[idx * WST + 50] = 0.f; g_w[idx * WST + 51] = 0.f; }
            const float ta = 0.075f;
            const float dba = (float)(0.088 - 0.075);
            const float dcb = (float)(1.0 - 0.088);
            float tw0 = fmaxf(fminf((w0 - ta) / dba, (1.0f - w0) / dcb), 0.f);
            float tw1 = fmaxf(fminf((w1 - ta) / dba, (1.0f - w1) / dcb), 0.f);
            int c0 = (lane < MM) ? (tw0 >= 0.6f ? 2 : (tw0 >= 0.1f ? 1 : 0)) : 0;
            int c1 = (lane + 32 < MM) ? (tw1 >= 0.6f ? 2 : (tw1 >= 0.1f ? 1 : 0)) : 0;
            unsigned b00 = __ballot_sync(0xffffffffu, c0 & 1);
            unsigned b01 = __ballot_sync(0xffffffffu, c0 >> 1);
            unsigned b10 = __ballot_sync(0xffffffffu, c1 & 1);
            unsigned b11 = __ballot_sync(0xffffffffu, c1 >> 1);
            if (lane == 0) {
                g_pack[idx * 2 + 0] = (unsigned long long)b00 | ((unsigned long long)b01 << 32);
                g_pack[idx * 2 + 1] = (unsigned long long)b10 | ((unsigned long long)b11 << 32);
            }
        }
    }
}

// ---------------- Kernel B: matched/prev via warp ballot backward scan ---------
__global__ __launch_bounds__(256) void kB() {
    const int gw = blockIdx.x * 8 + (threadIdx.x >> 5);
    const int lane = threadIdx.x & 31;
    const int b = gw / TT, i = gw % TT;
    const unsigned long long m0 = g_pack[gw * 2], m1 = g_pack[gw * 2 + 1];
    const unsigned long long* rp = &g_pack[(size_t)b * TT * 2];
    int prev = 0, matched = 0;
    for (int base = i - 1; base >= 0; base -= 32) {
        const int j = base - lane;
        const bool eq = (j >= 0) && (rp[j * 2] == m0) && (rp[j * 2 + 1] == m1);
        const unsigned msk = __ballot_sync(0xffffffffu, eq);
        if (msk) { matched = 1; prev = base - (__ffs(msk) - 1); break; }
    }
    if (lane == 0) { g_prev[gw] = prev; g_match[gw] = matched; }
}

// ---------------- Kernel C: fused memory-network scan --------------------------
// 256 threads: o = tid>>1, p = tid&1 (batch of the pair). 2 barriers/step.
// smem: fS 0..32768 | eS ..65536 | adS ..98304 | xh4[34] | fh4[34] | wbuf[2][2][56]
#define C_SMEM (98304 + 544 + 544 + 896)
__global__ __launch_bounds__(256) void kC(const int* __restrict__ qarr,
                                          const int* __restrict__ rarr,
                                          const float* __restrict__ fW,
                                          const float* __restrict__ Mv0) {
    extern __shared__ char sm[];
    uint4* fS = (uint4*)sm;
    uint4* eS = (uint4*)(sm + 32768);
    uint4* adS = (uint4*)(sm + 65536);
    uint4* xh4 = (uint4*)(sm + 98304);          // [34]: A@0, B@17
    uint4* fh4 = (uint4*)(sm + 98304 + 544);    // [34]
    float* wbuf = (float*)(sm + 98304 + 1088);  // [2 par][2 p][56]
    half2* xh2 = (half2*)xh4;
    half2* fh2 = (half2*)fh4;

    const int tid = threadIdx.x;
    const int o = tid >> 1, p = tid & 1;
    const int b0 = blockIdx.x * 2;
    const half2 z = __float2half2_rn(0.f);

    for (int i = tid; i < 64 * 128; i += 256) {
        const int jp = i >> 7, oo = i & 127;
        const int d = (((jp >> 2) * 128 + oo) << 2) + (jp & 3);
        ((half2*)fS)[d] = __floats2half2_rn(fW[oo * 256 + 2 * jp], fW[oo * 256 + 2 * jp + 1]);
        ((half2*)eS)[d] = __floats2half2_rn(g_We[oo * 128 + 2 * jp], g_We[oo * 128 + 2 * jp + 1]);
        ((half2*)adS)[d] = __floats2half2_rn(g_Wa[oo * 128 + 2 * jp], g_Wa[oo * 128 + 2 * jp + 1]);
    }
    float Mv[MM];
#pragma unroll
    for (int m = 0; m < MM; m++) Mv[m] = Mv0[m * DD + o];
    const float cev = g_ce[o], cav = g_ca[o];
    // prologue: stage w for t=0 into parity 0
    if (tid < WST) wbuf[tid] = g_w[(size_t)(b0 * TT) * WST + tid];
    else if (tid >= 128 && tid < 128 + WST) wbuf[56 + tid - 128] = g_w[(size_t)((b0 + 1) * TT) * WST + tid - 128];
    __syncthreads();

    int idxp = (b0 + p) * TT;
    for (int t = 0; t < TT; t++, idxp++) {
        const int par = (t & 1) * 112;
        // gathers (fp32, L2)
        const int qq = qarr[idxp];
        const int rr = rarr[idxp];
        const float kf = g_KF[(size_t)qq * DD + o];
        const float ge = rr ? g_Ae[(size_t)qq * DD + o] : 0.f;
        const float ga = rr ? g_Aa[(size_t)qq * DD + o] : 0.f;
        // phase 1: read = w . Mv
        const float4* w4 = (const float4*)&wbuf[par + p * 56];
        float r0 = 0.f, r1 = 0.f;
#pragma unroll
        for (int c = 0; c < 12; c++) {
            const float4 wv = w4[c];
            r0 = fmaf(wv.x, Mv[4 * c], r0);
            r1 = fmaf(wv.y, Mv[4 * c + 1], r1);
            r0 = fmaf(wv.z, Mv[4 * c + 2], r0);
            r1 = fmaf(wv.w, Mv[4 * c + 3], r1);
        }
        {
            const float4 wv = w4[12];
            r0 = fmaf(wv.x, Mv[48], r0);
            r1 = fmaf(wv.y, Mv[49], r1);
        }
        {
            const float rv = r0 + r1;
            const float rn = __shfl_xor_sync(0xffffffffu, rv, 2);
            if (!(tid & 2)) xh2[p * 68 + (o >> 1)] = __floats2half2_rn(rv, rn);
        }
        __syncthreads();  // B1

        // phase 2: f = tanh(read . fW_r^T + KF[q])
        half2 F[8] = {z, z, z, z, z, z, z, z};
#pragma unroll
        for (int j = 0; j < 16; j++) {
            const uint4 wv = fS[j * 128 + o];
            const uint4 xv = xh4[p * 17 + j];
            const int q4 = (j & 1) << 2;
            F[q4 + 0] = __hfma2(as_h2(wv.x), as_h2(xv.x), F[q4 + 0]);
            F[q4 + 1] = __hfma2(as_h2(wv.y), as_h2(xv.y), F[q4 + 1]);
            F[q4 + 2] = __hfma2(as_h2(wv.z), as_h2(xv.z), F[q4 + 2]);
            F[q4 + 3] = __hfma2(as_h2(wv.w), as_h2(xv.w), F[q4 + 3]);
        }
        float sf = kf;
#pragma unroll
        for (int qk = 0; qk < 8; qk++) sf += h2sumf(F[qk]);
        const float fv = ftanh(sf);
        g_f[(size_t)idxp * DD + o] = fv;
        {
            const float fn = __shfl_xor_sync(0xffffffffu, fv, 2);
            if (!(tid & 2)) fh2[p * 68 + (o >> 1)] = __floats2half2_rn(fv, fn);
        }
        // stage w for t+1 into the other parity slot
        if (t + 1 < TT) {
            const int npar = ((t + 1) & 1) * 112;
            if (tid < WST) wbuf[npar + tid] = g_w[(size_t)(b0 * TT + t + 1) * WST + tid];
            else if (tid >= 128 && tid < 128 + WST)
                wbuf[npar + 56 + tid - 128] = g_w[(size_t)((b0 + 1) * TT + t + 1) * WST + tid - 128];
        }
        __syncthreads();  // B2

        // phase 3: e = sig(f.We + r*Ae[q] + ce), a = tanh(f.Wa + r*Aa[q] + ca)
        half2 E[4] = {z, z, z, z}, Ag[4] = {z, z, z, z};
#pragma unroll
        for (int j = 0; j < 16; j++) {
            const uint4 we = eS[j * 128 + o];
            const uint4 wa = adS[j * 128 + o];
            const uint4 xv = fh4[p * 17 + j];
            E[0] = __hfma2(as_h2(we.x), as_h2(xv.x), E[0]);
            E[1] = __hfma2(as_h2(we.y), as_h2(xv.y), E[1]);
            E[2] = __hfma2(as_h2(we.z), as_h2(xv.z), E[2]);
            E[3] = __hfma2(as_h2(we.w), as_h2(xv.w), E[3]);
            Ag[0] = __hfma2(as_h2(wa.x), as_h2(xv.x), Ag[0]);
            Ag[1] = __hfma2(as_h2(wa.y), as_h2(xv.y), Ag[1]);
            Ag[2] = __hfma2(as_h2(wa.z), as_h2(xv.z), Ag[2]);
            Ag[3] = __hfma2(as_h2(wa.w), as_h2(xv.w), Ag[3]);
        }
        float se = ge + cev, sd = ga + cav;
#pragma unroll
        for (int qk = 0; qk < 4; qk++) {
            se += h2sumf(E[qk]);
            sd += h2sumf(Ag[qk]);
        }
        const float ev = sigf(se), av = ftanh(sd);
        // phase 4: Mv update
#pragma unroll
        for (int c = 0; c < 12; c++) {
            const float4 wv = w4[c];
            Mv[4 * c] = fmaf(wv.x, fmaf(-ev, Mv[4 * c], av), Mv[4 * c]);
            Mv[4 * c + 1] = fmaf(wv.y, fmaf(-ev, Mv[4 * c + 1], av), Mv[4 * c + 1]);
            Mv[4 * c + 2] = fmaf(wv.z, fmaf(-ev, Mv[4 * c + 2], av), Mv[4 * c + 2]);
            Mv[4 * c + 3] = fmaf(wv.w, fmaf(-ev, Mv[4 * c + 3], av), Mv[4 * c + 3]);
        }
        {
            const float4 wv = w4[12];
            Mv[48] = fmaf(wv.x, fmaf(-ev, Mv[48], av), Mv[48]);
            Mv[49] = fmaf(wv.y, fmaf(-ev, Mv[49], av), Mv[49]);
        }
    }
}

// ---------------- Kernel D: gi = f_all @ Wih.T + (bih + bhh) -------------------
__global__ __launch_bounds__(256) void kD(const float* __restrict__ Wih,
                                          const float* __restrict__ bih,
                                          const float* __restrict__ bhh) {
    __shared__ float sA[64][68];
    __shared__ float sB[64][68];
    const int tid = threadIdx.x;
    const int row0 = blockIdx.x * 64;
    const int n0 = blockIdx.y * 64;
    const int tx = tid & 15, ty = tid >> 4;
    float acc[4][4];
#pragma unroll
    for (int i = 0; i < 4; i++)
#pragma unroll
        for (int j = 0; j < 4; j++) acc[i][j] = 0.f;

    for (int kk = 0; kk < 128; kk += 64) {
        __syncthreads();
#pragma unroll
        for (int l = 0; l < 4; l++) {
            const int li = tid + l * 256;
            const int m = li >> 4;
            const int kq = li & 15;
            float4 v = *(const float4*)&g_f[(size_t)(row0 + m) * DD + kk + kq * 4];
            sA[kq * 4 + 0][m] = v.x; sA[kq * 4 + 1][m] = v.y;
            sA[kq * 4 + 2][m] = v.z; sA[kq * 4 + 3][m] = v.w;
            float4 u = *(const float4*)&Wih[(size_t)(n0 + m) * DD + kk + kq * 4];
            sB[kq * 4 + 0][m] = u.x; sB[kq * 4 + 1][m] = u.y;
            sB[kq * 4 + 2][m] = u.z; sB[kq * 4 + 3][m] = u.w;
        }
        __syncthreads();
#pragma unroll 8
        for (int k = 0; k < 64; k++) {
            float4 a4 = *(const float4*)&sA[k][ty * 4];
            float4 b4 = *(const float4*)&sB[k][tx * 4];
            acc[0][0] += a4.x * b4.x; acc[0][1] += a4.x * b4.y;
            acc[0][2] += a4.x * b4.z; acc[0][3] += a4.x * b4.w;
            acc[1][0] += a4.y * b4.x; acc[1][1] += a4.y * b4.y;
            acc[1][2] += a4.y * b4.z; acc[1][3] += a4.y * b4.w;
            acc[2][0] += a4.z * b4.x; acc[2][1] += a4.z * b4.y;
            acc[2][2] += a4.z * b4.z; acc[2][3] += a4.z * b4.w;
            acc[3][0] += a4.w * b4.x; acc[3][1] += a4.w * b4.y;
            acc[3][2] += a4.w * b4.z; acc[3][3] += a4.w * b4.w;
        }
    }
#pragma unroll
    for (int i = 0; i < 4; i++) {
        const int rrow = row0 + ty * 4 + i;
#pragma unroll
        for (int j = 0; j < 4; j++) {
            const int n = n0 + tx * 4 + j;
            g_gi[(size_t)rrow * G4 + n] = acc[i][j] + bih[n] + bhh[n];
        }
    }
}

// ---------------- Kernel E: LSTM scan, 1 batch/block, 512 thr, Whh in regs -----
__global__ __launch_bounds__(512) void kE(const float* __restrict__ Whh) {
    __shared__ uint4 hh4[17];
    __shared__ float gates[G4];
    half2* hh2 = (half2*)hh4;
    const int tid = threadIdx.x;
    const int b = blockIdx.x;

    half2 whh[64];
    {
        const float4* src = (const float4*)(Whh + (size_t)tid * DD);
#pragma unroll
        for (int j = 0; j < 32; j++) {
            const float4 v = src[j];
            whh[2 * j] = __floats2half2_rn(v.x, v.y);
            whh[2 * j + 1] = __floats2half2_rn(v.z, v.w);
        }
    }
    float h = 0.f, c = 0.f;
    __syncthreads();

    const half2 z = __float2half2_rn(0.f);
    int idx = b * TT;
    for (int t = 0; t < TT; t++, idx++) {
        float cin = 0.f;
        if (tid < 128) {
            float hv;
            if (g_match[idx]) {
                const int pv = g_prev[idx];
                hv = g_H[(size_t)(b * TT + pv) * DD + tid];
                cin = g_C[(size_t)(b * TT + pv) * DD + tid];
            } else {
                hv = h; cin = c;
            }
            const float hn = __shfl_xor_sync(0xffffffffu, hv, 1);
            if (!(tid & 1)) hh2[tid >> 1] = __floats2half2_rn(hv, hn);
        }
        const float gi = g_gi[(size_t)idx * G4 + tid];
        __syncthreads();  // B1

        half2 a0 = z, a1 = z, a2 = z, a3 = z;
#pragma unroll
        for (int j = 0; j < 16; j++) {
            const uint4 xv = hh4[j];
            a0 = __hfma2(whh[4 * j + 0], as_h2(xv.x), a0);
            a1 = __hfma2(whh[4 * j + 1], as_h2(xv.y), a1);
            a2 = __hfma2(whh[4 * j + 2], as_h2(xv.z), a2);
            a3 = __hfma2(whh[4 * j + 3], as_h2(xv.w), a3);
        }
        gates[tid] = gi + (h2sumf(a0) + h2sumf(a1)) + (h2sumf(a2) + h2sumf(a3));
        __syncthreads();  // B2

        if (tid < 128) {
            const float gI = gates[tid];
            const float gF = gates[128 + tid];
            const float gG = gates[256 + tid];
            const float gO = gates[384 + tid];
            c = sigf(gF) * cin + sigf(gI) * tanhf(gG);
            h = sigf(gO) * tanhf(c);
            g_H[(size_t)idx * DD + tid] = h;
            g_C[(size_t)idx * DD + tid] = c;
        }
    }
}

// ---------------- Kernel F: out = sigmoid(H . pW + pb) -------------------------
__global__ __launch_bounds__(256) void kF(const float* __restrict__ pW,
                                          const float* __restrict__ pb,
                                          float* __restrict__ out) {
    const int gw = blockIdx.x * 8 + (threadIdx.x >> 5);
    const int lane = threadIdx.x & 31;
    const float4 hv = ((const float4*)(g_H + (size_t)gw * DD))[lane];
    const float4 pv = ((const float4*)pW)[lane];
    float v = hv.x * pv.x + hv.y * pv.y + hv.z * pv.z + hv.w * pv.w;
    v = warp_sum(v);
    if (lane == 0) out[gw] = sigf(v + pb[0]);
}

// ---------------- launch ----------------
extern "C" void kernel_launch(void* const* d_in, const int* in_sizes, int n_in,
                              void* d_out, int out_size) {
    const int* q = (const int*)d_in[0];
    const int* r = (const int*)d_in[1];
    const float* k_emb = (const float*)d_in[2];
    const float* Mk = (const float*)d_in[3];
    const float* Mv0 = (const float*)d_in[4];
    const float* fW = (const float*)d_in[5];
    const float* fb = (const float*)d_in[6];
    const float* aW = (const float*)d_in[7];
    const float* ab = (const float*)d_in[8];
    const float* eW = (const float*)d_in[9];
    const float* eb = (const float*)d_in[10];
    const float* addW = (const float*)d_in[11];
    const float* addb = (const float*)d_in[12];
    const float* Wih = (const float*)d_in[13];
    const float* Whh = (const float*)d_in[14];
    const float* bih = (const float*)d_in[15];
    const float* bhh = (const float*)d_in[16];
    const float* pW = (const float*)d_in[17];
    const float* pb = (const float*)d_in[18];
    float* out = (float*)d_out;

    cudaFuncSetAttribute(kC, cudaFuncAttributeMaxDynamicSharedMemorySize, C_SMEM);

    kP0<<<128, 128>>>(aW, eW, addW, ab, eb, addb);
    kP1<<<dim3(128, 3), 128>>>(aW, eW, addW, k_emb, fW, fb);
    kA<<<256, 256>>>(q, r, k_emb, Mk);
    kB<<<RR / 8, 256>>>();
    kC<<<BSZ / 2, 256, C_SMEM>>>(q, r, fW, Mv0);
    kD<<<dim3(RR / 64, G4 / 64), 256>>>(Wih, bih, bhh);
    kE<<<BSZ, 512>>>(Whh);
    kF<<<RR / 8, 256>>>(pW, pb, out);
}